// round 8
// baseline (speedup 1.0000x reference)
#include <cuda_runtime.h>

// RoIAlign2D: features (4,256,96,96) f32, rois (1024,5) f32 -> out (1024,256,7,7) f32
// OUT_SIZE=7, SPATIAL_SCALE=0.0625, SAMPLE_NUM=2
//
// Block = (roi, 32-channel group). Stage the roi's feature patch for 32 channels
// in smem with channel-last layout [y][x][c] (c padded to 33), then compute with
// lane = channel: every tap LDS is a contiguous 128B read (1 phase), every STS
// during staging is stride-33 (conflict-free). Output transposed through smem
// so the final STG is coalesced.

#define CC     256
#define HH     96
#define WW     96
#define SCALE  0.0625f
#define PATCH  21     // max patch span: ceil(6.5 * max_bin) + 2 = 21
#define CPAD   33     // padded channel dim (conflict-free stride)
#define GROUP  32     // channels per block
#define NGRP   (CC / GROUP)   // 8

#define PATCH_ELEMS (PATCH * PATCH * CPAD)          // 14553 floats
#define SMEM_BYTES  ((PATCH_ELEMS + 49 * CPAD) * 4) // 64680 bytes

__global__ __launch_bounds__(256) void roi_align_smem(
    const float* __restrict__ feat,
    const float* __restrict__ rois,
    float* __restrict__ out)
{
    extern __shared__ float smem[];
    float* patch  = smem;                 // [PATCH][PATCH][CPAD]
    float* outbuf = smem + PATCH_ELEMS;   // [49][CPAD]

    int blk = blockIdx.x;
    int k   = blk >> 3;             // roi index (NGRP == 8 groups per roi)
    int c0  = (blk & (NGRP - 1)) * GROUP;

    const float* r = rois + k * 5;
    int   b  = (int)__ldg(r);
    float x1 = __ldg(r + 1) * SCALE;
    float y1 = __ldg(r + 2) * SCALE;
    float x2 = __ldg(r + 3) * SCALE;
    float y2 = __ldg(r + 4) * SCALE;

    float bw = fmaxf(x2 - x1, 1.0f) * (1.0f / 7.0f);
    float bh = fmaxf(y2 - y1, 1.0f) * (1.0f / 7.0f);

    // Patch origin = xlo/ylo of the very first sample (after clip). All taps of
    // all 14 samples lie in [origin, origin+20].
    float xc0 = fminf(fmaxf(x1 + bw * 0.25f, 0.0f), (float)(WW - 1));
    float yc0 = fminf(fmaxf(y1 + bh * 0.25f, 0.0f), (float)(HH - 1));
    int x0 = (int)floorf(xc0);
    int y0 = (int)floorf(yc0);

    int tid = threadIdx.x;

    // ---------------- stage patch: 32 channels x 21x21 ----------------
    const float* fbase = feat + (size_t)(b * CC + c0) * (HH * WW);
    for (int e = tid; e < GROUP * PATCH * PATCH; e += 256) {
        int c   = e / (PATCH * PATCH);
        int rem = e - c * (PATCH * PATCH);
        int y   = rem / PATCH;
        int j   = rem - y * PATCH;
        int gy = min(y0 + y, HH - 1);   // cells past the clamp edge are never read
        int gx = min(x0 + j, WW - 1);
        patch[(y * PATCH + j) * CPAD + c] =
            __ldg(fbase + (size_t)c * (HH * WW) + gy * WW + gx);
    }
    __syncthreads();

    // ---------------- compute: warp per output, lane = channel ----------------
    int w    = tid >> 5;
    int lane = tid & 31;
    for (int o = w; o < 49; o += 8) {
        int ph = o / 7;
        int pw = o - ph * 7;
        float acc = 0.0f;
        #pragma unroll
        for (int sy = 0; sy < 2; ++sy) {
            float yc  = y1 + bh * ((float)ph + 0.25f + 0.5f * (float)sy);
            bool  vy  = (yc >= -1.0f) && (yc <= (float)HH);
            float ycl = fminf(fmaxf(yc, 0.0f), (float)(HH - 1));
            float yfl = floorf(ycl);
            int   ylo = (int)yfl;
            int   yhi = min(ylo + 1, HH - 1);
            float fy  = ycl - yfl;
            float wyh = vy ? fy : 0.0f;
            float wyl = vy ? (1.0f - fy) : 0.0f;
            int tl = ylo - y0;
            int th = yhi - y0;
            #pragma unroll
            for (int sx = 0; sx < 2; ++sx) {
                float xc  = x1 + bw * ((float)pw + 0.25f + 0.5f * (float)sx);
                bool  vx  = (xc >= -1.0f) && (xc <= (float)WW);
                float xcl = fminf(fmaxf(xc, 0.0f), (float)(WW - 1));
                float xfl = floorf(xcl);
                int   xlo = (int)xfl;
                int   xhi = min(xlo + 1, WW - 1);
                float fx  = xcl - xfl;
                float wxh = vx ? fx : 0.0f;
                float wxl = vx ? (1.0f - fx) : 0.0f;
                int ul = xlo - x0;
                int uh = xhi - x0;

                float pll = patch[(tl * PATCH + ul) * CPAD + lane];
                float plh = patch[(tl * PATCH + uh) * CPAD + lane];
                float phl = patch[(th * PATCH + ul) * CPAD + lane];
                float phh = patch[(th * PATCH + uh) * CPAD + lane];
                acc += wyl * (wxl * pll + wxh * plh)
                     + wyh * (wxl * phl + wxh * phh);
            }
        }
        outbuf[o * CPAD + lane] = acc * 0.25f;
    }
    __syncthreads();

    // ---------------- coalesced writeback ----------------
    float* obase = out + ((size_t)k * CC + c0) * 49;
    for (int e = tid; e < GROUP * 49; e += 256) {
        int c = e / 49;
        int o = e - c * 49;
        obase[c * 49 + o] = outbuf[o * CPAD + c];   // stride-33 LDS: conflict-free
    }
}

extern "C" void kernel_launch(void* const* d_in, const int* in_sizes, int n_in,
                              void* d_out, int out_size)
{
    const float* feat = (const float*)d_in[0];
    const float* rois = (const float*)d_in[1];
    float*       out  = (float*)d_out;

    cudaFuncSetAttribute(roi_align_smem,
                         cudaFuncAttributeMaxDynamicSharedMemorySize, SMEM_BYTES);

    int n_rois = in_sizes[1] / 5;           // 1024
    int blocks = n_rois * NGRP;             // 8192
    roi_align_smem<<<blocks, 256, SMEM_BYTES>>>(feat, rois, out);
}

// round 10
// speedup vs baseline: 2.6890x; 2.6890x over previous
#include <cuda_runtime.h>

// RoIAlign2D: features (4,256,96,96) f32, rois (1024,5) f32 -> out (1024,256,7,7) f32
// OUT_SIZE=7, SPATIAL_SCALE=0.0625, SAMPLE_NUM=2
//
// Block = (roi, 32-channel group). v3:
//  - per-block sample-geometry tables (14 y + 14 x entries as float4)
//  - stage only the actual roi span (warp-per-row, lane=x, channel inner loop,
//    no div/mod, no clamping needed: span derived from clipped coords)
//  - compute with lane = channel: every tap LDS contiguous 128B (1 phase)
//  - output transposed through smem for coalesced STG

#define CC     256
#define HH     96
#define WW     96
#define SCALE  0.0625f
#define PATCH  21
#define CPAD   33
#define GROUP  32

#define PATCH_ELEMS  (PATCH * PATCH * CPAD)   // 14553
#define OUTBUF_ELEMS (49 * CPAD)              // 1617
#define TAB_FLOATS   (28 * 4)                 // 14 y + 14 x float4 entries
#define SMEM_BYTES   ((TAB_FLOATS + PATCH_ELEMS + OUTBUF_ELEMS) * 4)  // 65128

__global__ __launch_bounds__(256) void roi_align_v3(
    const float* __restrict__ feat,
    const float* __restrict__ rois,
    float* __restrict__ out)
{
    extern __shared__ float smem[];
    float4* ytab  = (float4*)smem;            // [14]
    float4* xtab  = (float4*)smem + 14;       // [14]
    float*  patch = smem + TAB_FLOATS;        // [PATCH][PATCH][CPAD]
    float*  outbuf= patch + PATCH_ELEMS;      // [49][CPAD]

    int blk = blockIdx.x;
    int k   = blk >> 3;
    int c0  = (blk & 7) * GROUP;

    const float* r = rois + k * 5;
    int   b  = (int)__ldg(r);
    float x1 = __ldg(r + 1) * SCALE;
    float y1 = __ldg(r + 2) * SCALE;
    float x2 = __ldg(r + 3) * SCALE;
    float y2 = __ldg(r + 4) * SCALE;

    float bw = fmaxf(x2 - x1, 1.0f) * (1.0f / 7.0f);
    float bh = fmaxf(y2 - y1, 1.0f) * (1.0f / 7.0f);

    // Patch origin = lo-tap of first sample; extent = hi-tap of last sample.
    // Sample coords are monotone, so these bound every tap; and since they are
    // computed from clipped coords, [x0..xmax] x [y0..ymax] is fully in-bounds.
    float xcf = fminf(fmaxf(x1 + bw * 0.25f, 0.0f), (float)(WW - 1));
    float ycf = fminf(fmaxf(y1 + bh * 0.25f, 0.0f), (float)(HH - 1));
    int x0 = (int)floorf(xcf);
    int y0 = (int)floorf(ycf);
    float xce = fminf(fmaxf(x1 + bw * 6.75f, 0.0f), (float)(WW - 1));
    float yce = fminf(fmaxf(y1 + bh * 6.75f, 0.0f), (float)(HH - 1));
    int xspan = min((int)floorf(xce) + 1, WW - 1) - x0 + 1;   // <= 21
    int yspan = min((int)floorf(yce) + 1, HH - 1) - y0 + 1;   // <= 21

    int tid  = threadIdx.x;
    int w    = tid >> 5;
    int lane = tid & 31;

    // ---- build sample geometry tables (threads 0..27, uniform-cheap) ----
    if (tid < 28) {
        bool  isY   = tid < 14;
        int   s     = isY ? tid : tid - 14;
        float start = isY ? y1 : x1;
        float bsz   = isY ? bh : bw;
        int   size  = isY ? HH : WW;
        int   org   = isY ? y0 : x0;
        int   mul   = isY ? (PATCH * CPAD) : CPAD;

        float c  = start + bsz * (0.25f + 0.5f * (float)s);
        bool  v  = (c >= -1.0f) && (c <= (float)size);
        float cc = fminf(fmaxf(c, 0.0f), (float)(size - 1));
        float fl = floorf(cc);
        int   lo = (int)fl;
        int   hi = min(lo + 1, size - 1);
        float fr = cc - fl;
        float4 e;
        e.x = __int_as_float((lo - org) * mul);
        e.y = __int_as_float((hi - org) * mul);
        e.z = v ? (1.0f - fr) : 0.0f;
        e.w = v ? fr : 0.0f;
        if (isY) ytab[s] = e; else xtab[s] = e;
    }

    // ---- stage patch: warp-per-row, lane = x, channel inner loop ----
    const float* fbase = feat + (size_t)(b * CC + c0) * (HH * WW);
    for (int y = w; y < yspan; y += 8) {
        if (lane < xspan) {
            const float* g = fbase + (y0 + y) * WW + x0 + lane;
            float*       p = patch + (y * PATCH + lane) * CPAD;
            #pragma unroll 8
            for (int c = 0; c < GROUP; ++c)
                p[c] = __ldg(g + c * (HH * WW));
        }
    }
    __syncthreads();

    // ---- compute: warp per output, lane = channel ----
    const float* plane = patch + lane;
    for (int o = w; o < 49; o += 8) {
        int ph = o / 7;
        int pw = o - ph * 7;
        float4 ya = ytab[2 * ph], yb = ytab[2 * ph + 1];
        float4 xa = xtab[2 * pw], xb = xtab[2 * pw + 1];
        float acc = 0.0f;
        #pragma unroll
        for (int sy = 0; sy < 2; ++sy) {
            float4 ye = sy ? yb : ya;
            int rl = __float_as_int(ye.x);
            int rh = __float_as_int(ye.y);
            #pragma unroll
            for (int sx = 0; sx < 2; ++sx) {
                float4 xe = sx ? xb : xa;
                int cl = __float_as_int(xe.x);
                int ch = __float_as_int(xe.y);
                float tll = plane[rl + cl];
                float tlh = plane[rl + ch];
                float thl = plane[rh + cl];
                float thh = plane[rh + ch];
                float tlo = xe.z * tll + xe.w * tlh;
                float thi = xe.z * thl + xe.w * thh;
                acc += ye.z * tlo + ye.w * thi;
            }
        }
        outbuf[o * CPAD + lane] = acc * 0.25f;
    }
    __syncthreads();

    // ---- coalesced writeback ----
    float* obase = out + ((size_t)k * CC + c0) * 49;
    for (int e = tid; e < GROUP * 49; e += 256) {
        int c = e / 49;
        int o = e - c * 49;
        obase[c * 49 + o] = outbuf[o * CPAD + c];
    }
}

extern "C" void kernel_launch(void* const* d_in, const int* in_sizes, int n_in,
                              void* d_out, int out_size)
{
    const float* feat = (const float*)d_in[0];
    const float* rois = (const float*)d_in[1];
    float*       out  = (float*)d_out;

    cudaFuncSetAttribute(roi_align_v3,
                         cudaFuncAttributeMaxDynamicSharedMemorySize, SMEM_BYTES);

    int n_rois = in_sizes[1] / 5;   // 1024
    roi_align_v3<<<n_rois * 8, 256, SMEM_BYTES>>>(feat, rois, out);
}